// round 2
// baseline (speedup 1.0000x reference)
#include <cuda_runtime.h>

#define NN 100000
#define NE 1000000
#define CH 128
#define ROWS 64
#define PAD 132

// Scratch (allocation-free rule: __device__ globals)
__device__ float g_cnt[NN];                 // degree -> reciprocal of max(deg,1)
__device__ float g_agg[(size_t)NN * CH];    // neighbor-sum buffer
__device__ float g_h[(size_t)NN * CH];      // hidden activations (reused in-place)

// ---------------------------------------------------------------- zero / degree
__global__ void k_zero_agg() {
    int i = blockIdx.x * blockDim.x + threadIdx.x;
    const int n4 = NN * CH / 4;
    if (i < n4) ((float4*)g_agg)[i] = make_float4(0.f, 0.f, 0.f, 0.f);
}

__global__ void k_zero_cnt() {
    int i = blockIdx.x * blockDim.x + threadIdx.x;
    if (i < NN) g_cnt[i] = 0.f;
}

__global__ void k_degree(const int* __restrict__ ei) {
    int e = blockIdx.x * blockDim.x + threadIdx.x;
    if (e < NE) atomicAdd(&g_cnt[ei[NE + e]], 1.0f);
}

__global__ void k_invcnt() {
    int i = blockIdx.x * blockDim.x + threadIdx.x;
    if (i < NN) g_cnt[i] = 1.0f / fmaxf(g_cnt[i], 1.0f);
}

// ---------------------------------------------------------------- scatter-add
// One warp per edge; lane l owns floats [4l, 4l+4) of the 128-dim feature row.
// Vector reduction (no return): 1 REDG.128 per lane per edge.
__global__ void k_scatter(const float* __restrict__ in, const int* __restrict__ ei) {
    int gt = blockIdx.x * blockDim.x + threadIdx.x;
    int w = gt >> 5;
    int l = gt & 31;
    if (w >= NE) return;
    int src = ei[w];
    int dst = ei[NE + w];
    float4 v = *(const float4*)(in + (size_t)src * CH + l * 4);
    float* a = g_agg + (size_t)dst * CH + l * 4;
    asm volatile("red.global.add.v4.f32 [%0], {%1,%2,%3,%4};"
                 :: "l"(a), "f"(v.x), "f"(v.y), "f"(v.z), "f"(v.w)
                 : "memory");
}

// ---------------------------------------------------------------- fused SAGE layer
// out[n] = relu( (agg[n]*invcnt[n]) @ wl + bl + in[n] @ wr )
// Block = 256 threads, 64 nodes. Both 128x128 weights + both input tiles in SMEM.
// Warp w handles 8 nodes; lane l handles output cols [4l, 4l+4).
__global__ void __launch_bounds__(256, 1)
k_layer(const float* __restrict__ in,
        const float* __restrict__ wl, const float* __restrict__ bl,
        const float* __restrict__ wr, float* __restrict__ out) {
    extern __shared__ float sm[];
    float* sWL = sm;                    // [128][128]
    float* sWR = sWL + CH * CH;         // [128][128]
    float* sX  = sWR + CH * CH;         // [64][132]
    float* sM  = sX + ROWS * PAD;       // [64][132]

    int tid = threadIdx.x;
    int base = blockIdx.x * ROWS;

    // Stage weights (row-major [k][j], identical layout in SMEM)
    for (int i = tid; i < CH * CH / 4; i += 256) {
        ((float4*)sWL)[i] = ((const float4*)wl)[i];
        ((float4*)sWR)[i] = ((const float4*)wr)[i];
    }
    // Stage node features + on-the-fly mean
    for (int i = tid; i < ROWS * (CH / 4); i += 256) {
        int r = i >> 5;            // CH/4 == 32
        int c = (i & 31) * 4;
        int n = base + r;
        float4 xv = make_float4(0.f, 0.f, 0.f, 0.f);
        float4 mv = xv;
        if (n < NN) {
            xv = *(const float4*)(in + (size_t)n * CH + c);
            float ic = g_cnt[n];
            float4 av = *(const float4*)(g_agg + (size_t)n * CH + c);
            mv.x = av.x * ic; mv.y = av.y * ic; mv.z = av.z * ic; mv.w = av.w * ic;
        }
        *(float4*)(sX + r * PAD + c) = xv;
        *(float4*)(sM + r * PAD + c) = mv;
    }
    __syncthreads();

    int w = tid >> 5, l = tid & 31;
    int r0 = w * 8;
    float4 acc[8];
#pragma unroll
    for (int i = 0; i < 8; i++) acc[i] = make_float4(0.f, 0.f, 0.f, 0.f);

#pragma unroll 4
    for (int k = 0; k < CH; k++) {
        float4 wlv = *(const float4*)(sWL + k * CH + l * 4);  // conflict-free LDS.128
        float4 wrv = *(const float4*)(sWR + k * CH + l * 4);
#pragma unroll
        for (int i = 0; i < 8; i++) {
            float mv = sM[(r0 + i) * PAD + k];  // broadcast
            float xv = sX[(r0 + i) * PAD + k];  // broadcast
            acc[i].x = fmaf(mv, wlv.x, fmaf(xv, wrv.x, acc[i].x));
            acc[i].y = fmaf(mv, wlv.y, fmaf(xv, wrv.y, acc[i].y));
            acc[i].z = fmaf(mv, wlv.z, fmaf(xv, wrv.z, acc[i].z));
            acc[i].w = fmaf(mv, wlv.w, fmaf(xv, wrv.w, acc[i].w));
        }
    }

    float4 bv = *(const float4*)(bl + l * 4);
#pragma unroll
    for (int i = 0; i < 8; i++) {
        int n = base + r0 + i;
        if (n < NN) {
            float4 o;
            o.x = fmaxf(acc[i].x + bv.x, 0.f);
            o.y = fmaxf(acc[i].y + bv.y, 0.f);
            o.z = fmaxf(acc[i].z + bv.z, 0.f);
            o.w = fmaxf(acc[i].w + bv.w, 0.f);
            *(float4*)(out + (size_t)n * CH + l * 4) = o;
        }
    }
}

// ---------------------------------------------------------------- classifier
// One warp per node: logits[n] = h[n] @ w_cls + b_cls   (128 -> 3)
__global__ void k_cls(const float* __restrict__ h, const float* __restrict__ wc,
                      const float* __restrict__ bc, float* __restrict__ out) {
    __shared__ float sw[CH * 3];
    __shared__ float sb[3];
    for (int i = threadIdx.x; i < CH * 3; i += blockDim.x) sw[i] = wc[i];
    if (threadIdx.x < 3) sb[threadIdx.x] = bc[threadIdx.x];
    __syncthreads();

    int gt = blockIdx.x * blockDim.x + threadIdx.x;
    int n = gt >> 5;
    int l = gt & 31;
    if (n >= NN) return;

    float4 hv = *(const float4*)(h + (size_t)n * CH + l * 4);
    int f = l * 4;
    float p0 = hv.x * sw[(f + 0) * 3 + 0] + hv.y * sw[(f + 1) * 3 + 0]
             + hv.z * sw[(f + 2) * 3 + 0] + hv.w * sw[(f + 3) * 3 + 0];
    float p1 = hv.x * sw[(f + 0) * 3 + 1] + hv.y * sw[(f + 1) * 3 + 1]
             + hv.z * sw[(f + 2) * 3 + 1] + hv.w * sw[(f + 3) * 3 + 1];
    float p2 = hv.x * sw[(f + 0) * 3 + 2] + hv.y * sw[(f + 1) * 3 + 2]
             + hv.z * sw[(f + 2) * 3 + 2] + hv.w * sw[(f + 3) * 3 + 2];
#pragma unroll
    for (int off = 16; off; off >>= 1) {
        p0 += __shfl_down_sync(0xFFFFFFFFu, p0, off);
        p1 += __shfl_down_sync(0xFFFFFFFFu, p1, off);
        p2 += __shfl_down_sync(0xFFFFFFFFu, p2, off);
    }
    if (l == 0) {
        out[(size_t)n * 3 + 0] = p0 + sb[0];
        out[(size_t)n * 3 + 1] = p1 + sb[1];
        out[(size_t)n * 3 + 2] = p2 + sb[2];
    }
}

// ---------------------------------------------------------------- launch
extern "C" void kernel_launch(void* const* d_in, const int* in_sizes, int n_in,
                              void* d_out, int out_size) {
    const float* x   = (const float*)d_in[0];
    const int*   ei  = (const int*)d_in[1];
    const float* wl1 = (const float*)d_in[2];
    const float* bl1 = (const float*)d_in[3];
    const float* wr1 = (const float*)d_in[4];
    const float* wl2 = (const float*)d_in[5];
    const float* bl2 = (const float*)d_in[6];
    const float* wr2 = (const float*)d_in[7];
    const float* wc  = (const float*)d_in[8];
    const float* bc  = (const float*)d_in[9];
    float* out = (float*)d_out;

    float* hbuf = nullptr;
    cudaGetSymbolAddress((void**)&hbuf, g_h);

    const size_t smem = (size_t)(2 * CH * CH + 2 * ROWS * PAD) * sizeof(float);
    cudaFuncSetAttribute(k_layer, cudaFuncAttributeMaxDynamicSharedMemorySize, (int)smem);

    const int Z4   = (NN * CH / 4 + 255) / 256;
    const int ZN   = (NN + 255) / 256;
    const int EB   = (NE + 255) / 256;
    const int SCB  = (int)(((size_t)NE * 32) / 256);       // exact: 125000
    const int LYB  = (NN + ROWS - 1) / ROWS;               // 1563
    const int CLB  = (int)(((size_t)NN * 32 + 255) / 256); // 12500

    // degree (shared by both layers)
    k_zero_cnt<<<ZN, 256>>>();
    k_degree<<<EB, 256>>>(ei);
    k_invcnt<<<ZN, 256>>>();

    // layer 1
    k_zero_agg<<<Z4, 256>>>();
    k_scatter<<<SCB, 256>>>(x, ei);
    k_layer<<<LYB, 256, smem>>>(x, wl1, bl1, wr1, hbuf);

    // layer 2 (in-place on g_h: each block only reads its own rows before writing)
    k_zero_agg<<<Z4, 256>>>();
    k_scatter<<<SCB, 256>>>(hbuf, ei);
    k_layer<<<LYB, 256, smem>>>(hbuf, wl2, bl2, wr2, hbuf);

    // classifier
    k_cls<<<CLB, 256>>>(hbuf, wc, bc, out);
}

// round 4
// speedup vs baseline: 1.4437x; 1.4437x over previous
#include <cuda_runtime.h>
#include <cuda_bf16.h>
#include <cstdint>

#define NN 100000
#define NE 1000000
#define CH 128
#define MTILE 128
#define LYB ((NN + MTILE - 1) / MTILE)   // 782

// ---------------- scratch (__device__ globals; no allocation) ----------------
__device__ float g_cnt[NN];
__device__ float g_agg[(size_t)NN * CH];
__device__ float g_h[(size_t)NN * CH];
// prepared weights: [layer][tile: WlH,WlL,WrH,WrL][n=128][k=128] bf16 (transposed + split)
__device__ __nv_bfloat16 g_wprep[2 * 4 * 128 * 128];

// ---------------- SMEM map (bytes) ----------------
#define ASTRIDE 272              // 128 bf16 + 8 pad
#define BSTRIDE 144              // 64 bf16 + 8 pad
#define SA_T(t) ((t) * 34816)    // 0 meanH, 1 meanL, 2 xH, 3 xL
#define SB_OFF  139264
#define SB_T(t) (SB_OFF + (t) * 18432)
#define S_BIAS  212992
#define SMEM_TOTAL 213504

// ---------------- helpers ----------------
__device__ __forceinline__ uint32_t smem_u32(const void* p) {
    uint32_t a;
    asm("{ .reg .u64 t; cvta.to.shared.u64 t, %1; cvt.u32.u64 %0, t; }" : "=r"(a) : "l"(p));
    return a;
}
__device__ __forceinline__ void ldsm4(uint32_t* r, uint32_t addr) {
    asm volatile("ldmatrix.sync.aligned.m8n8.x4.shared.b16 {%0,%1,%2,%3}, [%4];"
                 : "=r"(r[0]), "=r"(r[1]), "=r"(r[2]), "=r"(r[3]) : "r"(addr));
}
__device__ __forceinline__ void hmma(float* c, const uint32_t* a, uint32_t b0, uint32_t b1) {
    asm volatile(
        "mma.sync.aligned.m16n8k16.row.col.f32.bf16.bf16.f32 "
        "{%0,%1,%2,%3}, {%4,%5,%6,%7}, {%8,%9}, {%0,%1,%2,%3};"
        : "+f"(c[0]), "+f"(c[1]), "+f"(c[2]), "+f"(c[3])
        : "r"(a[0]), "r"(a[1]), "r"(a[2]), "r"(a[3]), "r"(b0), "r"(b1));
}
__device__ __forceinline__ unsigned split_pair(float a, float b, unsigned& lo) {
    __nv_bfloat16 ha = __float2bfloat16(a), hb = __float2bfloat16(b);
    __nv_bfloat16 la = __float2bfloat16(a - __bfloat162float(ha));
    __nv_bfloat16 lb = __float2bfloat16(b - __bfloat162float(hb));
    lo = (unsigned)__bfloat16_as_ushort(la) | ((unsigned)__bfloat16_as_ushort(lb) << 16);
    return (unsigned)__bfloat16_as_ushort(ha) | ((unsigned)__bfloat16_as_ushort(hb) << 16);
}

// ---------------- zero / degree ----------------
__global__ void k_zero_agg() {
    int i = blockIdx.x * blockDim.x + threadIdx.x;
    if (i < NN * CH / 4) ((float4*)g_agg)[i] = make_float4(0.f, 0.f, 0.f, 0.f);
}
__global__ void k_zero_cnt() {
    int i = blockIdx.x * blockDim.x + threadIdx.x;
    if (i < NN) g_cnt[i] = 0.f;
}
__global__ void k_degree(const int* __restrict__ ei) {
    int e = blockIdx.x * blockDim.x + threadIdx.x;
    if (e < NE) atomicAdd(&g_cnt[ei[NE + e]], 1.0f);
}
__global__ void k_invcnt() {
    int i = blockIdx.x * blockDim.x + threadIdx.x;
    if (i < NN) g_cnt[i] = 1.0f / fmaxf(g_cnt[i], 1.0f);
}

// ---------------- weight prep: fp32 [k][n] -> bf16 hi/lo, transposed [n][k] ----------------
__global__ void k_wprep(const float* __restrict__ wl1, const float* __restrict__ wr1,
                        const float* __restrict__ wl2, const float* __restrict__ wr2) {
    int idx = blockIdx.x * blockDim.x + threadIdx.x;   // [layer][ws][k][n]
    if (idx >= 2 * 2 * 128 * 128) return;
    int n = idx & 127;
    int k = (idx >> 7) & 127;
    int ws = (idx >> 14) & 1;
    int layer = idx >> 15;
    const float* src = layer ? (ws ? wr2 : wl2) : (ws ? wr1 : wl1);
    float v = src[k * 128 + n];
    __nv_bfloat16 hi = __float2bfloat16(v);
    __nv_bfloat16 lo = __float2bfloat16(v - __bfloat162float(hi));
    size_t b = (size_t)(layer * 4 + ws * 2) * 16384 + (size_t)n * 128 + k;
    g_wprep[b] = hi;
    g_wprep[b + 16384] = lo;
}

// ---------------- scatter-add (REDG.v4, one warp per edge) ----------------
__global__ void k_scatter(const float* __restrict__ in, const int* __restrict__ ei) {
    int gt = blockIdx.x * blockDim.x + threadIdx.x;
    int w = gt >> 5, l = gt & 31;
    if (w >= NE) return;
    int src = ei[w], dst = ei[NE + w];
    float4 v = *(const float4*)(in + (size_t)src * CH + l * 4);
    float* a = g_agg + (size_t)dst * CH + l * 4;
    asm volatile("red.global.add.v4.f32 [%0], {%1,%2,%3,%4};"
                 :: "l"(a), "f"(v.x), "f"(v.y), "f"(v.z), "f"(v.w) : "memory");
}

// ---------------- fused SAGE layer via mma.sync bf16-split ----------------
// out = relu( mean @ wl + bl + in @ wr ), M=128 per CTA, 256 threads (8 warps 4x2).
__global__ void __launch_bounds__(256, 1)
k_layer(const float* __restrict__ in, const float* __restrict__ bl,
        float* __restrict__ out, int layer) {
    extern __shared__ __align__(1024) char smem[];
    uint32_t sbase = smem_u32(smem);
    int tid = threadIdx.x;
    int wid = tid >> 5, lid = tid & 31;
    int warp_m = wid & 3, warp_n = wid >> 2;
    int base = blockIdx.x * MTILE;

    if (tid < 128) *(float*)(smem + S_BIAS + tid * 4) = bl[tid];

    // ---- stage A: 2 threads per node row; split fp32 -> bf16 hi/lo ----
    {
        int row = tid >> 1;
        int c0 = (tid & 1) * 64;
        int n = base + row;
        bool valid = (n < NN);
        const float4* xr = (const float4*)(in + (size_t)n * CH + c0);
        const float4* ar = (const float4*)(g_agg + (size_t)n * CH + c0);
        float ic = valid ? g_cnt[n] : 0.f;
#pragma unroll 4
        for (int c4 = 0; c4 < 16; c4++) {
            float4 xv = make_float4(0.f, 0.f, 0.f, 0.f), av = xv;
            if (valid) { xv = xr[c4]; av = ar[c4]; }
            float m[4] = {av.x * ic, av.y * ic, av.z * ic, av.w * ic};
            float xx[4] = {xv.x, xv.y, xv.z, xv.w};
            int c = c0 + c4 * 4;
#pragma unroll
            for (int p = 0; p < 2; p++) {
                int off = row * ASTRIDE + (c + p * 2) * 2;
                unsigned lo, hi;
                hi = split_pair(m[p * 2], m[p * 2 + 1], lo);
                *(unsigned*)(smem + SA_T(0) + off) = hi;
                *(unsigned*)(smem + SA_T(1) + off) = lo;
                hi = split_pair(xx[p * 2], xx[p * 2 + 1], lo);
                *(unsigned*)(smem + SA_T(2) + off) = hi;
                *(unsigned*)(smem + SA_T(3) + off) = lo;
            }
        }
    }

    float c[2][8][4];
#pragma unroll
    for (int mt = 0; mt < 2; mt++)
#pragma unroll
        for (int nt = 0; nt < 8; nt++)
#pragma unroll
            for (int j = 0; j < 4; j++) c[mt][nt][j] = 0.f;

    // lane-invariant pieces of LDSM addresses
    int a_row = warp_m * 32 + (lid & 15);         // + mt*16
    int a_kb = ((lid >> 4) << 3) * 2;             // k sub-block bytes
    int b_n = warp_n * 64 + (lid & 7) + ((lid >> 4) << 3);   // + p*16
    int b_kb = (((lid >> 3) & 1) << 3) * 2;

    // term tables: A tile {mH,mH,mL,xH,xH,xL}, B tile {WlH,WlL,WlH,WrH,WrL,WrH}
    const int ta[6] = {0, 0, 1, 2, 2, 3};
    const int tbt[6] = {0, 1, 0, 2, 3, 2};

    for (int kh = 0; kh < 2; kh++) {
        if (kh) __syncthreads();
        // stage B half: 4 tiles x 128n x 64k bf16
        {
            const __nv_bfloat16* wbase = g_wprep + (size_t)layer * 65536 + (size_t)kh * 64;
            for (int i = tid; i < 4096; i += 256) {
                int tile = i >> 10, rem = i & 1023;
                int n = rem >> 3, chv = rem & 7;
                *(float4*)(smem + SB_T(tile) + n * BSTRIDE + chv * 16) =
                    *(const float4*)(wbase + ((size_t)tile * 16384 + (size_t)n * 128) + chv * 8);
            }
        }
        __syncthreads();

#pragma unroll 1
        for (int ks = 0; ks < 4; ks++) {
            int k0b = (kh * 64 + ks * 16) * 2;
            uint32_t af[4][8];
#pragma unroll
            for (int at = 0; at < 4; at++) {
#pragma unroll
                for (int mt = 0; mt < 2; mt++)
                    ldsm4(&af[at][mt * 4],
                          sbase + SA_T(at) + (a_row + mt * 16) * ASTRIDE + k0b + a_kb);
            }
            int kloc = ks * 32 + b_kb;   // local k bytes within half
#pragma unroll
            for (int t = 0; t < 6; t++) {
                uint32_t bf[4][4];
#pragma unroll
                for (int p = 0; p < 4; p++)
                    ldsm4(bf[p], sbase + SB_T(tbt[t]) + (b_n + p * 16) * BSTRIDE + kloc);
#pragma unroll
                for (int mt = 0; mt < 2; mt++)
#pragma unroll
                    for (int nt = 0; nt < 8; nt++)
                        hmma(c[mt][nt], &af[ta[t]][mt * 4],
                             bf[nt >> 1][(nt & 1) * 2], bf[nt >> 1][(nt & 1) * 2 + 1]);
            }
        }
    }

    // ---- epilogue: bias + relu + store ----
#pragma unroll
    for (int mt = 0; mt < 2; mt++) {
        int r0 = base + warp_m * 32 + mt * 16 + (lid >> 2);
#pragma unroll
        for (int nt = 0; nt < 8; nt++) {
            int col = warp_n * 64 + nt * 8 + (lid & 3) * 2;
            float b0 = *(float*)(smem + S_BIAS + col * 4);
            float b1 = *(float*)(smem + S_BIAS + (col + 1) * 4);
            if (r0 < NN) {
                float2 v;
                v.x = fmaxf(c[mt][nt][0] + b0, 0.f);
                v.y = fmaxf(c[mt][nt][1] + b1, 0.f);
                *(float2*)(out + (size_t)r0 * CH + col) = v;
            }
            if (r0 + 8 < NN) {
                float2 v;
                v.x = fmaxf(c[mt][nt][2] + b0, 0.f);
                v.y = fmaxf(c[mt][nt][3] + b1, 0.f);
                *(float2*)(out + (size_t)(r0 + 8) * CH + col) = v;
            }
        }
    }
}

// ---------------- classifier ----------------
__global__ void k_cls(const float* __restrict__ h, const float* __restrict__ wc,
                      const float* __restrict__ bc, float* __restrict__ out) {
    __shared__ float sw[CH * 3];
    __shared__ float sb[3];
    for (int i = threadIdx.x; i < CH * 3; i += blockDim.x) sw[i] = wc[i];
    if (threadIdx.x < 3) sb[threadIdx.x] = bc[threadIdx.x];
    __syncthreads();
    int gt = blockIdx.x * blockDim.x + threadIdx.x;
    int n = gt >> 5, l = gt & 31;
    if (n >= NN) return;
    float4 hv = *(const float4*)(h + (size_t)n * CH + l * 4);
    int f = l * 4;
    float p0 = hv.x * sw[(f + 0) * 3 + 0] + hv.y * sw[(f + 1) * 3 + 0]
             + hv.z * sw[(f + 2) * 3 + 0] + hv.w * sw[(f + 3) * 3 + 0];
    float p1 = hv.x * sw[(f + 0) * 3 + 1] + hv.y * sw[(f + 1) * 3 + 1]
             + hv.z * sw[(f + 2) * 3 + 1] + hv.w * sw[(f + 3) * 3 + 1];
    float p2 = hv.x * sw[(f + 0) * 3 + 2] + hv.y * sw[(f + 1) * 3 + 2]
             + hv.z * sw[(f + 2) * 3 + 2] + hv.w * sw[(f + 3) * 3 + 2];
#pragma unroll
    for (int off = 16; off; off >>= 1) {
        p0 += __shfl_down_sync(0xFFFFFFFFu, p0, off);
        p1 += __shfl_down_sync(0xFFFFFFFFu, p1, off);
        p2 += __shfl_down_sync(0xFFFFFFFFu, p2, off);
    }
    if (l == 0) {
        out[(size_t)n * 3 + 0] = p0 + sb[0];
        out[(size_t)n * 3 + 1] = p1 + sb[1];
        out[(size_t)n * 3 + 2] = p2 + sb[2];
    }
}

// ---------------- launch ----------------
extern "C" void kernel_launch(void* const* d_in, const int* in_sizes, int n_in,
                              void* d_out, int out_size) {
    const float* x   = (const float*)d_in[0];
    const int*   ei  = (const int*)d_in[1];
    const float* wl1 = (const float*)d_in[2];
    const float* bl1 = (const float*)d_in[3];
    const float* wr1 = (const float*)d_in[4];
    const float* wl2 = (const float*)d_in[5];
    const float* bl2 = (const float*)d_in[6];
    const float* wr2 = (const float*)d_in[7];
    const float* wc  = (const float*)d_in[8];
    const float* bc  = (const float*)d_in[9];
    float* out = (float*)d_out;

    float* hbuf = nullptr;
    cudaGetSymbolAddress((void**)&hbuf, g_h);

    cudaFuncSetAttribute(k_layer, cudaFuncAttributeMaxDynamicSharedMemorySize, SMEM_TOTAL);

    const int Z4  = (NN * CH / 4 + 255) / 256;
    const int ZN  = (NN + 255) / 256;
    const int EB  = (NE + 255) / 256;
    const int SCB = (int)(((size_t)NE * 32) / 256);
    const int CLB = (int)(((size_t)NN * 32 + 255) / 256);

    // degree (shared) + weight prep (shared)
    k_zero_cnt<<<ZN, 256>>>();
    k_degree<<<EB, 256>>>(ei);
    k_invcnt<<<ZN, 256>>>();
    k_wprep<<<(2 * 2 * 128 * 128 + 255) / 256, 256>>>(wl1, wr1, wl2, wr2);

    // layer 1
    k_zero_agg<<<Z4, 256>>>();
    k_scatter<<<SCB, 256>>>(x, ei);
    k_layer<<<LYB, 256, SMEM_TOTAL>>>(x, bl1, hbuf, 0);

    // layer 2 (in-place: each CTA reads only its own rows before writing)
    k_zero_agg<<<Z4, 256>>>();
    k_scatter<<<SCB, 256>>>(hbuf, ei);
    k_layer<<<LYB, 256, SMEM_TOTAL>>>(hbuf, bl2, hbuf, 1);

    // classifier
    k_cls<<<CLB, 256>>>(hbuf, wc, bc, out);
}

// round 5
// speedup vs baseline: 2.0028x; 1.3873x over previous
#include <cuda_runtime.h>
#include <cuda_bf16.h>
#include <cstdint>

#define NN 100000
#define NE 1000000
#define CH 128
#define MTILE 128
#define LYB ((NN + MTILE - 1) / MTILE)   // 782
#define SCAN_B ((NN + 255) / 256)        // 391

// ---------------- scratch (__device__ globals; no allocation) ----------------
__device__ int g_deg[NN];
__device__ int g_rowptr[NN + 1];
__device__ int g_bsum[SCAN_B];
__device__ int g_cur[NN];
__device__ int g_nbr[NE];
__device__ float g_mean[(size_t)NN * CH];
__device__ float g_h[(size_t)NN * CH];
// prepared weights: [layer][tile: WlH,WlL,WrH,WrL][n=128][k=128] bf16 (transposed + split)
__device__ __nv_bfloat16 g_wprep[2 * 4 * 128 * 128];

// ---------------- SMEM map (bytes) ----------------
#define ASTRIDE 272              // 128 bf16 + 8 pad
#define BSTRIDE 144              // 64 bf16 + 8 pad
#define SA_T(t) ((t) * 34816)    // 0 meanH, 1 meanL, 2 xH, 3 xL
#define SB_OFF  139264
#define SB_T(t) (SB_OFF + (t) * 18432)
#define S_BIAS  212992
#define SMEM_TOTAL 213504

// ---------------- helpers ----------------
__device__ __forceinline__ uint32_t smem_u32(const void* p) {
    uint32_t a;
    asm("{ .reg .u64 t; cvta.to.shared.u64 t, %1; cvt.u32.u64 %0, t; }" : "=r"(a) : "l"(p));
    return a;
}
__device__ __forceinline__ void ldsm4(uint32_t* r, uint32_t addr) {
    asm volatile("ldmatrix.sync.aligned.m8n8.x4.shared.b16 {%0,%1,%2,%3}, [%4];"
                 : "=r"(r[0]), "=r"(r[1]), "=r"(r[2]), "=r"(r[3]) : "r"(addr));
}
__device__ __forceinline__ void hmma(float* c, const uint32_t* a, uint32_t b0, uint32_t b1) {
    asm volatile(
        "mma.sync.aligned.m16n8k16.row.col.f32.bf16.bf16.f32 "
        "{%0,%1,%2,%3}, {%4,%5,%6,%7}, {%8,%9}, {%0,%1,%2,%3};"
        : "+f"(c[0]), "+f"(c[1]), "+f"(c[2]), "+f"(c[3])
        : "r"(a[0]), "r"(a[1]), "r"(a[2]), "r"(a[3]), "r"(b0), "r"(b1));
}
__device__ __forceinline__ unsigned split_pair(float a, float b, unsigned& lo) {
    __nv_bfloat16 ha = __float2bfloat16(a), hb = __float2bfloat16(b);
    __nv_bfloat16 la = __float2bfloat16(a - __bfloat162float(ha));
    __nv_bfloat16 lb = __float2bfloat16(b - __bfloat162float(hb));
    lo = (unsigned)__bfloat16_as_ushort(la) | ((unsigned)__bfloat16_as_ushort(lb) << 16);
    return (unsigned)__bfloat16_as_ushort(ha) | ((unsigned)__bfloat16_as_ushort(hb) << 16);
}

// ---------------- CSR build ----------------
__global__ void k_zero_deg() {
    int i = blockIdx.x * blockDim.x + threadIdx.x;
    if (i < NN) g_deg[i] = 0;
}
__global__ void k_degree(const int* __restrict__ ei) {
    int e = blockIdx.x * blockDim.x + threadIdx.x;
    if (e < NE) atomicAdd(&g_deg[ei[NE + e]], 1);
}
// per-256-block exclusive scan; block totals to g_bsum
__global__ void k_scan_block() {
    __shared__ int ws[8];
    int i = blockIdx.x * 256 + threadIdx.x;
    int lane = threadIdx.x & 31, warp = threadIdx.x >> 5;
    int v = (i < NN) ? g_deg[i] : 0;
    int s = v;
#pragma unroll
    for (int o = 1; o < 32; o <<= 1) {
        int t = __shfl_up_sync(0xFFFFFFFFu, s, o);
        if (lane >= o) s += t;
    }
    if (lane == 31) ws[warp] = s;
    __syncthreads();
    if (warp == 0) {
        int t = (lane < 8) ? ws[lane] : 0;
#pragma unroll
        for (int o = 1; o < 8; o <<= 1) {
            int u = __shfl_up_sync(0xFFFFFFFFu, t, o);
            if (lane >= o) t += u;
        }
        if (lane < 8) ws[lane] = t;
    }
    __syncthreads();
    int off = warp ? ws[warp - 1] : 0;
    if (i < NN) g_rowptr[i] = s + off - v;   // block-local exclusive
    if (threadIdx.x == 255) g_bsum[blockIdx.x] = s + off;
}
// exclusive scan of the 391 block sums (single block, 512 threads)
__global__ void k_scan_sums() {
    __shared__ int ws[16];
    int t = threadIdx.x, lane = t & 31, warp = t >> 5;
    int v = (t < SCAN_B) ? g_bsum[t] : 0;
    int s = v;
#pragma unroll
    for (int o = 1; o < 32; o <<= 1) {
        int u = __shfl_up_sync(0xFFFFFFFFu, s, o);
        if (lane >= o) s += u;
    }
    if (lane == 31) ws[warp] = s;
    __syncthreads();
    if (warp == 0) {
        int u = (lane < 16) ? ws[lane] : 0;
#pragma unroll
        for (int o = 1; o < 16; o <<= 1) {
            int w = __shfl_up_sync(0xFFFFFFFFu, u, o);
            if (lane >= o) u += w;
        }
        if (lane < 16) ws[lane] = u;
    }
    __syncthreads();
    int off = warp ? ws[warp - 1] : 0;
    if (t < SCAN_B) g_bsum[t] = s + off - v;
}
__global__ void k_scan_apply() {
    int i = blockIdx.x * 256 + threadIdx.x;
    if (i < NN) {
        int r = g_rowptr[i] + g_bsum[blockIdx.x];
        g_rowptr[i] = r;
        g_cur[i] = r;
    }
    if (i == 0) g_rowptr[NN] = NE;
}
__global__ void k_fill(const int* __restrict__ ei) {
    int e = blockIdx.x * blockDim.x + threadIdx.x;
    if (e >= NE) return;
    int dst = ei[NE + e];
    int pos = atomicAdd(&g_cur[dst], 1);
    g_nbr[pos] = ei[e];
}

// ---------------- gather + mean: one warp per dst node ----------------
__global__ void __launch_bounds__(256)
k_gather(const float* __restrict__ in) {
    int gw = (blockIdx.x * blockDim.x + threadIdx.x) >> 5;
    int lid = threadIdx.x & 31;
    if (gw >= NN) return;
    int beg = g_rowptr[gw], end = g_rowptr[gw + 1];
    float4 acc = make_float4(0.f, 0.f, 0.f, 0.f);
    for (int j0 = beg; j0 < end; j0 += 32) {
        int cnt = min(32, end - j0);
        int idx = (j0 + lid < end) ? g_nbr[j0 + lid] : 0;
#pragma unroll 4
        for (int jj = 0; jj < cnt; jj++) {
            int src = __shfl_sync(0xFFFFFFFFu, idx, jj);
            float4 v = *(const float4*)(in + (size_t)src * CH + lid * 4);
            acc.x += v.x; acc.y += v.y; acc.z += v.z; acc.w += v.w;
        }
    }
    float sc = 1.0f / fmaxf((float)(end - beg), 1.0f);
    acc.x *= sc; acc.y *= sc; acc.z *= sc; acc.w *= sc;
    *(float4*)(g_mean + (size_t)gw * CH + lid * 4) = acc;
}

// ---------------- weight prep: fp32 [k][n] -> bf16 hi/lo, transposed [n][k] ----------------
__global__ void k_wprep(const float* __restrict__ wl1, const float* __restrict__ wr1,
                        const float* __restrict__ wl2, const float* __restrict__ wr2) {
    int idx = blockIdx.x * blockDim.x + threadIdx.x;   // [layer][ws][k][n]
    if (idx >= 2 * 2 * 128 * 128) return;
    int n = idx & 127;
    int k = (idx >> 7) & 127;
    int ws = (idx >> 14) & 1;
    int layer = idx >> 15;
    const float* src = layer ? (ws ? wr2 : wl2) : (ws ? wr1 : wl1);
    float v = src[k * 128 + n];
    __nv_bfloat16 hi = __float2bfloat16(v);
    __nv_bfloat16 lo = __float2bfloat16(v - __bfloat162float(hi));
    size_t b = (size_t)(layer * 4 + ws * 2) * 16384 + (size_t)n * 128 + k;
    g_wprep[b] = hi;
    g_wprep[b + 16384] = lo;
}

// ---------------- fused SAGE layer via mma.sync bf16-split ----------------
// out = relu( mean @ wl + bl + in @ wr ), M=128 per CTA, 256 threads (8 warps 4x2).
__global__ void __launch_bounds__(256, 1)
k_layer(const float* __restrict__ in, const float* __restrict__ bl,
        float* __restrict__ out, int layer) {
    extern __shared__ __align__(1024) char smem[];
    uint32_t sbase = smem_u32(smem);
    int tid = threadIdx.x;
    int wid = tid >> 5, lid = tid & 31;
    int warp_m = wid & 3, warp_n = wid >> 2;
    int base = blockIdx.x * MTILE;

    if (tid < 128) *(float*)(smem + S_BIAS + tid * 4) = bl[tid];

    // ---- stage A: 2 threads per node row; split fp32 -> bf16 hi/lo ----
    {
        int row = tid >> 1;
        int c0 = (tid & 1) * 64;
        int n = base + row;
        bool valid = (n < NN);
        const float4* xr = (const float4*)(in + (size_t)n * CH + c0);
        const float4* mr = (const float4*)(g_mean + (size_t)n * CH + c0);
#pragma unroll 4
        for (int c4 = 0; c4 < 16; c4++) {
            float4 xv = make_float4(0.f, 0.f, 0.f, 0.f), mv = xv;
            if (valid) { xv = xr[c4]; mv = mr[c4]; }
            float m[4] = {mv.x, mv.y, mv.z, mv.w};
            float xx[4] = {xv.x, xv.y, xv.z, xv.w};
            int c = c0 + c4 * 4;
#pragma unroll
            for (int p = 0; p < 2; p++) {
                int off = row * ASTRIDE + (c + p * 2) * 2;
                unsigned lo, hi;
                hi = split_pair(m[p * 2], m[p * 2 + 1], lo);
                *(unsigned*)(smem + SA_T(0) + off) = hi;
                *(unsigned*)(smem + SA_T(1) + off) = lo;
                hi = split_pair(xx[p * 2], xx[p * 2 + 1], lo);
                *(unsigned*)(smem + SA_T(2) + off) = hi;
                *(unsigned*)(smem + SA_T(3) + off) = lo;
            }
        }
    }

    float c[2][8][4];
#pragma unroll
    for (int mt = 0; mt < 2; mt++)
#pragma unroll
        for (int nt = 0; nt < 8; nt++)
#pragma unroll
            for (int j = 0; j < 4; j++) c[mt][nt][j] = 0.f;

    // lane-invariant pieces of LDSM addresses
    int a_row = warp_m * 32 + (lid & 15);         // + mt*16
    int a_kb = ((lid >> 4) << 3) * 2;             // k sub-block bytes
    int b_n = warp_n * 64 + (lid & 7) + ((lid >> 4) << 3);   // + p*16
    int b_kb = (((lid >> 3) & 1) << 3) * 2;

    // term tables: A tile {mH,mH,mL,xH,xH,xL}, B tile {WlH,WlL,WlH,WrH,WrL,WrH}
    const int ta[6] = {0, 0, 1, 2, 2, 3};
    const int tbt[6] = {0, 1, 0, 2, 3, 2};

    for (int kh = 0; kh < 2; kh++) {
        if (kh) __syncthreads();
        // stage B half: 4 tiles x 128n x 64k bf16
        {
            const __nv_bfloat16* wbase = g_wprep + (size_t)layer * 65536 + (size_t)kh * 64;
            for (int i = tid; i < 4096; i += 256) {
                int tile = i >> 10, rem = i & 1023;
                int n = rem >> 3, chv = rem & 7;
                *(float4*)(smem + SB_T(tile) + n * BSTRIDE + chv * 16) =
                    *(const float4*)(wbase + ((size_t)tile * 16384 + (size_t)n * 128) + chv * 8);
            }
        }
        __syncthreads();

#pragma unroll 1
        for (int ks = 0; ks < 4; ks++) {
            int k0b = (kh * 64 + ks * 16) * 2;
            uint32_t af[4][8];
#pragma unroll
            for (int at = 0; at < 4; at++) {
#pragma unroll
                for (int mt = 0; mt < 2; mt++)
                    ldsm4(&af[at][mt * 4],
                          sbase + SA_T(at) + (a_row + mt * 16) * ASTRIDE + k0b + a_kb);
            }
            int kloc = ks * 32 + b_kb;   // local k bytes within half
#pragma unroll
            for (int t = 0; t < 6; t++) {
                uint32_t bf[4][4];
#pragma unroll
                for (int p = 0; p < 4; p++)
                    ldsm4(bf[p], sbase + SB_T(tbt[t]) + (b_n + p * 16) * BSTRIDE + kloc);
#pragma unroll
                for (int mt = 0; mt < 2; mt++)
#pragma unroll
                    for (int nt = 0; nt < 8; nt++)
                        hmma(c[mt][nt], &af[ta[t]][mt * 4],
                             bf[nt >> 1][(nt & 1) * 2], bf[nt >> 1][(nt & 1) * 2 + 1]);
            }
        }
    }

    // ---- epilogue: bias + relu + store ----
#pragma unroll
    for (int mt = 0; mt < 2; mt++) {
        int r0 = base + warp_m * 32 + mt * 16 + (lid >> 2);
#pragma unroll
        for (int nt = 0; nt < 8; nt++) {
            int col = warp_n * 64 + nt * 8 + (lid & 3) * 2;
            float b0 = *(float*)(smem + S_BIAS + col * 4);
            float b1 = *(float*)(smem + S_BIAS + (col + 1) * 4);
            if (r0 < NN) {
                float2 v;
                v.x = fmaxf(c[mt][nt][0] + b0, 0.f);
                v.y = fmaxf(c[mt][nt][1] + b1, 0.f);
                *(float2*)(out + (size_t)r0 * CH + col) = v;
            }
            if (r0 + 8 < NN) {
                float2 v;
                v.x = fmaxf(c[mt][nt][2] + b0, 0.f);
                v.y = fmaxf(c[mt][nt][3] + b1, 0.f);
                *(float2*)(out + (size_t)(r0 + 8) * CH + col) = v;
            }
        }
    }
}

// ---------------- classifier ----------------
__global__ void k_cls(const float* __restrict__ h, const float* __restrict__ wc,
                      const float* __restrict__ bc, float* __restrict__ out) {
    __shared__ float sw[CH * 3];
    __shared__ float sb[3];
    for (int i = threadIdx.x; i < CH * 3; i += blockDim.x) sw[i] = wc[i];
    if (threadIdx.x < 3) sb[threadIdx.x] = bc[threadIdx.x];
    __syncthreads();
    int gt = blockIdx.x * blockDim.x + threadIdx.x;
    int n = gt >> 5, l = gt & 31;
    if (n >= NN) return;
    float4 hv = *(const float4*)(h + (size_t)n * CH + l * 4);
    int f = l * 4;
    float p0 = hv.x * sw[(f + 0) * 3 + 0] + hv.y * sw[(f + 1) * 3 + 0]
             + hv.z * sw[(f + 2) * 3 + 0] + hv.w * sw[(f + 3) * 3 + 0];
    float p1 = hv.x * sw[(f + 0) * 3 + 1] + hv.y * sw[(f + 1) * 3 + 1]
             + hv.z * sw[(f + 2) * 3 + 1] + hv.w * sw[(f + 3) * 3 + 1];
    float p2 = hv.x * sw[(f + 0) * 3 + 2] + hv.y * sw[(f + 1) * 3 + 2]
             + hv.z * sw[(f + 2) * 3 + 2] + hv.w * sw[(f + 3) * 3 + 2];
#pragma unroll
    for (int off = 16; off; off >>= 1) {
        p0 += __shfl_down_sync(0xFFFFFFFFu, p0, off);
        p1 += __shfl_down_sync(0xFFFFFFFFu, p1, off);
        p2 += __shfl_down_sync(0xFFFFFFFFu, p2, off);
    }
    if (l == 0) {
        out[(size_t)n * 3 + 0] = p0 + sb[0];
        out[(size_t)n * 3 + 1] = p1 + sb[1];
        out[(size_t)n * 3 + 2] = p2 + sb[2];
    }
}

// ---------------- launch ----------------
extern "C" void kernel_launch(void* const* d_in, const int* in_sizes, int n_in,
                              void* d_out, int out_size) {
    const float* x   = (const float*)d_in[0];
    const int*   ei  = (const int*)d_in[1];
    const float* wl1 = (const float*)d_in[2];
    const float* bl1 = (const float*)d_in[3];
    const float* wr1 = (const float*)d_in[4];
    const float* wl2 = (const float*)d_in[5];
    const float* bl2 = (const float*)d_in[6];
    const float* wr2 = (const float*)d_in[7];
    const float* wc  = (const float*)d_in[8];
    const float* bc  = (const float*)d_in[9];
    float* out = (float*)d_out;

    float* hbuf = nullptr;
    cudaGetSymbolAddress((void**)&hbuf, g_h);

    cudaFuncSetAttribute(k_layer, cudaFuncAttributeMaxDynamicSharedMemorySize, SMEM_TOTAL);

    const int ZN  = (NN + 255) / 256;
    const int EB  = (NE + 255) / 256;
    const int GWB = (int)(((size_t)NN * 32 + 255) / 256);  // 12500 warps-blocks
    const int CLB = (int)(((size_t)NN * 32 + 255) / 256);

    // CSR build (shared by both layers) + weight prep
    k_zero_deg<<<ZN, 256>>>();
    k_degree<<<EB, 256>>>(ei);
    k_scan_block<<<SCAN_B, 256>>>();
    k_scan_sums<<<1, 512>>>();
    k_scan_apply<<<SCAN_B, 256>>>();
    k_fill<<<EB, 256>>>(ei);
    k_wprep<<<(2 * 2 * 128 * 128 + 255) / 256, 256>>>(wl1, wr1, wl2, wr2);

    // layer 1
    k_gather<<<GWB, 256>>>(x);
    k_layer<<<LYB, 256, SMEM_TOTAL>>>(x, bl1, hbuf, 0);

    // layer 2 (in-place: each CTA reads only its own rows before writing)
    k_gather<<<GWB, 256>>>(hbuf);
    k_layer<<<LYB, 256, SMEM_TOTAL>>>(hbuf, bl2, hbuf, 1);

    // classifier
    k_cls<<<CLB, 256>>>(hbuf, wc, bc, out);
}

// round 6
// speedup vs baseline: 2.2628x; 1.1298x over previous
#include <cuda_runtime.h>
#include <cuda_fp16.h>
#include <cstdint>

#define NN 100000
#define NE 1000000
#define CH 128
#define MTILE 128
#define LYB ((NN + MTILE - 1) / MTILE)   // 782
#define SCAN_B ((NN + 255) / 256)        // 391

// ---------------- scratch (__device__ globals; no allocation) ----------------
__device__ int g_deg[NN];
__device__ int g_rowptr[NN + 1];
__device__ int g_bsum[SCAN_B];
__device__ int g_cur[NN];
__device__ int g_nbr[NE];
__device__ float g_mean[(size_t)NN * CH];
__device__ float g_h[(size_t)NN * CH];
// prepared weights: [layer][w: Wl,Wr][n=128][k=128] fp16 (transposed)
__device__ __half g_wprep[2 * 2 * 128 * 128];

// ---------------- SMEM map (bytes) ----------------
#define ASTRIDE 272              // 128 fp16 + 8 pad
#define BSTRIDE 272              // 128 fp16 + 16 pad (stride%128B=16 -> conflict-free LDSM)
#define SA_T(t) ((t) * 34816)    // 0 meanH, 1 meanL, 2 xH, 3 xL
#define SB_T(t) (139264 + (t) * 34816)   // 0 Wl, 1 Wr (full K resident)
#define S_BIAS  208896           // 128 f32
#define S_WC    209408           // 128x3 f32
#define S_CLS   210944           // 128x3 f32 partial logits
#define S_BC    212480           // 3 f32 + pad
#define SMEM_TOTAL 212496

// ---------------- helpers ----------------
__device__ __forceinline__ uint32_t smem_u32(const void* p) {
    uint32_t a;
    asm("{ .reg .u64 t; cvta.to.shared.u64 t, %1; cvt.u32.u64 %0, t; }" : "=r"(a) : "l"(p));
    return a;
}
__device__ __forceinline__ void ldsm4(uint32_t* r, uint32_t addr) {
    asm volatile("ldmatrix.sync.aligned.m8n8.x4.shared.b16 {%0,%1,%2,%3}, [%4];"
                 : "=r"(r[0]), "=r"(r[1]), "=r"(r[2]), "=r"(r[3]) : "r"(addr));
}
__device__ __forceinline__ void hmma(float* c, const uint32_t* a, uint32_t b0, uint32_t b1) {
    asm volatile(
        "mma.sync.aligned.m16n8k16.row.col.f32.f16.f16.f32 "
        "{%0,%1,%2,%3}, {%4,%5,%6,%7}, {%8,%9}, {%0,%1,%2,%3};"
        : "+f"(c[0]), "+f"(c[1]), "+f"(c[2]), "+f"(c[3])
        : "r"(a[0]), "r"(a[1]), "r"(a[2]), "r"(a[3]), "r"(b0), "r"(b1));
}
// split two fp32 into fp16 hi pair (ret) and fp16 lo pair (out lo)
__device__ __forceinline__ unsigned split_pair(float a, float b, unsigned& lo) {
    __half ha = __float2half_rn(a), hb = __float2half_rn(b);
    __half la = __float2half_rn(a - __half2float(ha));
    __half lb = __float2half_rn(b - __half2float(hb));
    lo = (unsigned)__half_as_ushort(la) | ((unsigned)__half_as_ushort(lb) << 16);
    return (unsigned)__half_as_ushort(ha) | ((unsigned)__half_as_ushort(hb) << 16);
}

// ---------------- CSR build ----------------
__global__ void k_zero_deg() {
    int i = blockIdx.x * blockDim.x + threadIdx.x;
    if (i < NN) g_deg[i] = 0;
}
__global__ void k_degree(const int* __restrict__ ei) {
    int e = blockIdx.x * blockDim.x + threadIdx.x;
    if (e < NE) atomicAdd(&g_deg[ei[NE + e]], 1);
}
__global__ void k_scan_block() {
    __shared__ int ws[8];
    int i = blockIdx.x * 256 + threadIdx.x;
    int lane = threadIdx.x & 31, warp = threadIdx.x >> 5;
    int v = (i < NN) ? g_deg[i] : 0;
    int s = v;
#pragma unroll
    for (int o = 1; o < 32; o <<= 1) {
        int t = __shfl_up_sync(0xFFFFFFFFu, s, o);
        if (lane >= o) s += t;
    }
    if (lane == 31) ws[warp] = s;
    __syncthreads();
    if (warp == 0) {
        int t = (lane < 8) ? ws[lane] : 0;
#pragma unroll
        for (int o = 1; o < 8; o <<= 1) {
            int u = __shfl_up_sync(0xFFFFFFFFu, t, o);
            if (lane >= o) t += u;
        }
        if (lane < 8) ws[lane] = t;
    }
    __syncthreads();
    int off = warp ? ws[warp - 1] : 0;
    if (i < NN) g_rowptr[i] = s + off - v;
    if (threadIdx.x == 255) g_bsum[blockIdx.x] = s + off;
}
__global__ void k_scan_sums() {
    __shared__ int ws[16];
    int t = threadIdx.x, lane = t & 31, warp = t >> 5;
    int v = (t < SCAN_B) ? g_bsum[t] : 0;
    int s = v;
#pragma unroll
    for (int o = 1; o < 32; o <<= 1) {
        int u = __shfl_up_sync(0xFFFFFFFFu, s, o);
        if (lane >= o) s += u;
    }
    if (lane == 31) ws[warp] = s;
    __syncthreads();
    if (warp == 0) {
        int u = (lane < 16) ? ws[lane] : 0;
#pragma unroll
        for (int o = 1; o < 16; o <<= 1) {
            int w = __shfl_up_sync(0xFFFFFFFFu, u, o);
            if (lane >= o) u += w;
        }
        if (lane < 16) ws[lane] = u;
    }
    __syncthreads();
    int off = warp ? ws[warp - 1] : 0;
    if (t < SCAN_B) g_bsum[t] = s + off - v;
}
__global__ void k_scan_apply() {
    int i = blockIdx.x * 256 + threadIdx.x;
    if (i < NN) {
        int r = g_rowptr[i] + g_bsum[blockIdx.x];
        g_rowptr[i] = r;
        g_cur[i] = r;
    }
    if (i == 0) g_rowptr[NN] = NE;
}
__global__ void k_fill(const int* __restrict__ ei) {
    int e = blockIdx.x * blockDim.x + threadIdx.x;
    if (e >= NE) return;
    int dst = ei[NE + e];
    int pos = atomicAdd(&g_cur[dst], 1);
    g_nbr[pos] = ei[e];
}

// ---------------- gather + mean: one warp per dst node ----------------
__global__ void __launch_bounds__(256)
k_gather(const float* __restrict__ in) {
    int gw = (blockIdx.x * blockDim.x + threadIdx.x) >> 5;
    int lid = threadIdx.x & 31;
    if (gw >= NN) return;
    int beg = g_rowptr[gw], end = g_rowptr[gw + 1];
    float4 acc = make_float4(0.f, 0.f, 0.f, 0.f);
    for (int j0 = beg; j0 < end; j0 += 32) {
        int cnt = min(32, end - j0);
        int idx = (j0 + lid < end) ? g_nbr[j0 + lid] : 0;
#pragma unroll 4
        for (int jj = 0; jj < cnt; jj++) {
            int src = __shfl_sync(0xFFFFFFFFu, idx, jj);
            float4 v = *(const float4*)(in + (size_t)src * CH + lid * 4);
            acc.x += v.x; acc.y += v.y; acc.z += v.z; acc.w += v.w;
        }
    }
    float sc = 1.0f / fmaxf((float)(end - beg), 1.0f);
    acc.x *= sc; acc.y *= sc; acc.z *= sc; acc.w *= sc;
    *(float4*)(g_mean + (size_t)gw * CH + lid * 4) = acc;
}

// ---------------- weight prep: fp32 [k][n] -> fp16 transposed [n][k] ----------------
__global__ void k_wprep(const float* __restrict__ wl1, const float* __restrict__ wr1,
                        const float* __restrict__ wl2, const float* __restrict__ wr2) {
    int idx = blockIdx.x * blockDim.x + threadIdx.x;   // [layer][ws][k][n]
    if (idx >= 2 * 2 * 128 * 128) return;
    int n = idx & 127;
    int k = (idx >> 7) & 127;
    int ws = (idx >> 14) & 1;
    int layer = idx >> 15;
    const float* src = layer ? (ws ? wr2 : wl2) : (ws ? wr1 : wl1);
    g_wprep[(size_t)(layer * 2 + ws) * 16384 + (size_t)n * 128 + k] =
        __float2half_rn(src[k * 128 + n]);
}

// ---------------- fused SAGE layer via mma.sync fp16 4-term ----------------
// hout = relu( mean @ wl + bl + in @ wr ); if do_cls: out = h @ wc + bc instead.
__global__ void __launch_bounds__(256, 1)
k_layer(const float* __restrict__ in, const float* __restrict__ bl,
        float* __restrict__ hout, int layer, int do_cls,
        const float* __restrict__ wc, const float* __restrict__ bc,
        float* __restrict__ cls_out) {
    extern __shared__ __align__(1024) char smem[];
    uint32_t sbase = smem_u32(smem);
    int tid = threadIdx.x;
    int wid = tid >> 5, lid = tid & 31;
    int warp_m = wid & 3, warp_n = wid >> 2;
    int base = blockIdx.x * MTILE;

    if (tid < 128) *(float*)(smem + S_BIAS + tid * 4) = bl[tid];
    if (do_cls) {
        for (int i = tid; i < 384; i += 256) {
            *(float*)(smem + S_WC + i * 4) = wc[i];
            *(float*)(smem + S_CLS + i * 4) = 0.f;
        }
        if (tid < 3) *(float*)(smem + S_BC + tid * 4) = bc[tid];
    }

    // ---- stage B: full-K fp16 Wl, Wr ----
    {
        const __half* wbase = g_wprep + (size_t)layer * 32768;
        for (int i = tid; i < 4096; i += 256) {
            int tile = i >> 11, rem = i & 2047;
            int n = rem >> 4, ch = rem & 15;
            *(float4*)(smem + SB_T(tile) + n * BSTRIDE + ch * 16) =
                *(const float4*)(wbase + (size_t)tile * 16384 + (size_t)n * 128 + ch * 8);
        }
    }

    // ---- stage A: 2 threads per node row; split fp32 -> fp16 hi/lo ----
    {
        int row = tid >> 1;
        int c0 = (tid & 1) * 64;
        int n = base + row;
        bool valid = (n < NN);
        const float4* xr = (const float4*)(in + (size_t)n * CH + c0);
        const float4* mr = (const float4*)(g_mean + (size_t)n * CH + c0);
#pragma unroll 4
        for (int c4 = 0; c4 < 16; c4++) {
            float4 xv = make_float4(0.f, 0.f, 0.f, 0.f), mv = xv;
            if (valid) { xv = xr[c4]; mv = mr[c4]; }
            float m[4] = {mv.x, mv.y, mv.z, mv.w};
            float xx[4] = {xv.x, xv.y, xv.z, xv.w};
            int c = c0 + c4 * 4;
#pragma unroll
            for (int p = 0; p < 2; p++) {
                int off = row * ASTRIDE + (c + p * 2) * 2;
                unsigned lo, hi;
                hi = split_pair(m[p * 2], m[p * 2 + 1], lo);
                *(unsigned*)(smem + SA_T(0) + off) = hi;
                *(unsigned*)(smem + SA_T(1) + off) = lo;
                hi = split_pair(xx[p * 2], xx[p * 2 + 1], lo);
                *(unsigned*)(smem + SA_T(2) + off) = hi;
                *(unsigned*)(smem + SA_T(3) + off) = lo;
            }
        }
    }
    __syncthreads();

    float c[2][8][4];
#pragma unroll
    for (int mt = 0; mt < 2; mt++)
#pragma unroll
        for (int nt = 0; nt < 8; nt++)
#pragma unroll
            for (int j = 0; j < 4; j++) c[mt][nt][j] = 0.f;

    int a_row = warp_m * 32 + (lid & 15);
    int a_kb = ((lid >> 4) << 3) * 2;
    int b_n = warp_n * 64 + (lid & 7) + ((lid >> 4) << 3);
    int b_kb = (((lid >> 3) & 1) << 3) * 2;

#pragma unroll 1
    for (int ks = 0; ks < 8; ks++) {
        int k0b = ks * 32;
        uint32_t af[4][8];
#pragma unroll
        for (int at = 0; at < 4; at++)
#pragma unroll
            for (int mt = 0; mt < 2; mt++)
                ldsm4(&af[at][mt * 4],
                      sbase + SA_T(at) + (a_row + mt * 16) * ASTRIDE + k0b + a_kb);
        // B tile bt feeds A tiles {2bt, 2bt+1}: (meanH,meanL)->Wl, (xH,xL)->Wr
#pragma unroll
        for (int bt = 0; bt < 2; bt++) {
            uint32_t bf[4][4];
#pragma unroll
            for (int p = 0; p < 4; p++)
                ldsm4(bf[p], sbase + SB_T(bt) + (b_n + p * 16) * BSTRIDE + k0b + b_kb);
#pragma unroll
            for (int t = 0; t < 2; t++) {
                int at = bt * 2 + t;
#pragma unroll
                for (int mt = 0; mt < 2; mt++)
#pragma unroll
                    for (int nt = 0; nt < 8; nt++)
                        hmma(c[mt][nt], &af[at][mt * 4],
                             bf[nt >> 1][(nt & 1) * 2], bf[nt >> 1][(nt & 1) * 2 + 1]);
            }
        }
    }

    // ---- epilogue ----
    if (!do_cls) {
#pragma unroll
        for (int mt = 0; mt < 2; mt++) {
            int r0 = base + warp_m * 32 + mt * 16 + (lid >> 2);
#pragma unroll
            for (int nt = 0; nt < 8; nt++) {
                int col = warp_n * 64 + nt * 8 + (lid & 3) * 2;
                float b0 = *(float*)(smem + S_BIAS + col * 4);
                float b1 = *(float*)(smem + S_BIAS + (col + 1) * 4);
                if (r0 < NN) {
                    float2 v;
                    v.x = fmaxf(c[mt][nt][0] + b0, 0.f);
                    v.y = fmaxf(c[mt][nt][1] + b1, 0.f);
                    *(float2*)(hout + (size_t)r0 * CH + col) = v;
                }
                if (r0 + 8 < NN) {
                    float2 v;
                    v.x = fmaxf(c[mt][nt][2] + b0, 0.f);
                    v.y = fmaxf(c[mt][nt][3] + b1, 0.f);
                    *(float2*)(hout + (size_t)(r0 + 8) * CH + col) = v;
                }
            }
        }
    } else {
        // fused classifier: partial logits over this warp's 64-col slice
        float p[2][2][3];
#pragma unroll
        for (int mt = 0; mt < 2; mt++)
#pragma unroll
            for (int rh = 0; rh < 2; rh++)
#pragma unroll
                for (int cc = 0; cc < 3; cc++) p[mt][rh][cc] = 0.f;
#pragma unroll
        for (int mt = 0; mt < 2; mt++)
#pragma unroll
            for (int nt = 0; nt < 8; nt++) {
                int col = warp_n * 64 + nt * 8 + (lid & 3) * 2;
                float b0 = *(float*)(smem + S_BIAS + col * 4);
                float b1 = *(float*)(smem + S_BIAS + (col + 1) * 4);
                float v0 = fmaxf(c[mt][nt][0] + b0, 0.f);
                float v1 = fmaxf(c[mt][nt][1] + b1, 0.f);
                float v2 = fmaxf(c[mt][nt][2] + b0, 0.f);
                float v3 = fmaxf(c[mt][nt][3] + b1, 0.f);
#pragma unroll
                for (int cc = 0; cc < 3; cc++) {
                    float w0 = *(float*)(smem + S_WC + (col * 3 + cc) * 4);
                    float w1 = *(float*)(smem + S_WC + ((col + 1) * 3 + cc) * 4);
                    p[mt][0][cc] += v0 * w0 + v1 * w1;
                    p[mt][1][cc] += v2 * w0 + v3 * w1;
                }
            }
        // reduce across the 4 lanes sharing a row
#pragma unroll
        for (int o = 1; o < 4; o <<= 1)
#pragma unroll
            for (int mt = 0; mt < 2; mt++)
#pragma unroll
                for (int rh = 0; rh < 2; rh++)
#pragma unroll
                    for (int cc = 0; cc < 3; cc++)
                        p[mt][rh][cc] += __shfl_xor_sync(0xFFFFFFFFu, p[mt][rh][cc], o);
        // cross-warp combine (warp_n 0 then 1), deterministic
        if (warp_n == 0 && (lid & 3) == 0) {
#pragma unroll
            for (int mt = 0; mt < 2; mt++)
#pragma unroll
                for (int rh = 0; rh < 2; rh++) {
                    int lr = warp_m * 32 + mt * 16 + rh * 8 + (lid >> 2);
#pragma unroll
                    for (int cc = 0; cc < 3; cc++)
                        *(float*)(smem + S_CLS + (lr * 3 + cc) * 4) = p[mt][rh][cc];
                }
        }
        __syncthreads();
        if (warp_n == 1 && (lid & 3) == 0) {
#pragma unroll
            for (int mt = 0; mt < 2; mt++)
#pragma unroll
                for (int rh = 0; rh < 2; rh++) {
                    int lr = warp_m * 32 + mt * 16 + rh * 8 + (lid >> 2);
#pragma unroll
                    for (int cc = 0; cc < 3; cc++)
                        *(float*)(smem + S_CLS + (lr * 3 + cc) * 4) += p[mt][rh][cc];
                }
        }
        __syncthreads();
        if (tid < 128) {
            int n = base + tid;
            if (n < NN) {
#pragma unroll
                for (int cc = 0; cc < 3; cc++)
                    cls_out[(size_t)n * 3 + cc] =
                        *(float*)(smem + S_CLS + (tid * 3 + cc) * 4) +
                        *(float*)(smem + S_BC + cc * 4);
            }
        }
    }
}

// ---------------- launch ----------------
extern "C" void kernel_launch(void* const* d_in, const int* in_sizes, int n_in,
                              void* d_out, int out_size) {
    const float* x   = (const float*)d_in[0];
    const int*   ei  = (const int*)d_in[1];
    const float* wl1 = (const float*)d_in[2];
    const float* bl1 = (const float*)d_in[3];
    const float* wr1 = (const float*)d_in[4];
    const float* wl2 = (const float*)d_in[5];
    const float* bl2 = (const float*)d_in[6];
    const float* wr2 = (const float*)d_in[7];
    const float* wc  = (const float*)d_in[8];
    const float* bc  = (const float*)d_in[9];
    float* out = (float*)d_out;

    float* hbuf = nullptr;
    cudaGetSymbolAddress((void**)&hbuf, g_h);

    cudaFuncSetAttribute(k_layer, cudaFuncAttributeMaxDynamicSharedMemorySize, SMEM_TOTAL);

    const int ZN  = (NN + 255) / 256;
    const int EB  = (NE + 255) / 256;
    const int GWB = (int)(((size_t)NN * 32 + 255) / 256);

    // CSR build (shared by both layers) + weight prep
    k_zero_deg<<<ZN, 256>>>();
    k_degree<<<EB, 256>>>(ei);
    k_scan_block<<<SCAN_B, 256>>>();
    k_scan_sums<<<1, 512>>>();
    k_scan_apply<<<SCAN_B, 256>>>();
    k_fill<<<EB, 256>>>(ei);
    k_wprep<<<(2 * 2 * 128 * 128 + 255) / 256, 256>>>(wl1, wr1, wl2, wr2);

    // layer 1
    k_gather<<<GWB, 256>>>(x);
    k_layer<<<LYB, 256, SMEM_TOTAL>>>(x, bl1, hbuf, 0, 0, wc, bc, out);

    // layer 2 + fused classifier (h never written)
    k_gather<<<GWB, 256>>>(hbuf);
    k_layer<<<LYB, 256, SMEM_TOTAL>>>(hbuf, bl2, nullptr, 1, 1, wc, bc, out);
}